// round 14
// baseline (speedup 1.0000x reference)
#include <cuda_runtime.h>
#include <cstdint>

// Problem constants (fixed by the reference)
#define Nn 100000
#define Ee 600000
#define D  128
#define K2 256               // stacked K (mean | x)
#define NB_SCAN 391          // ceil(Nn/256)
#define THREADS 384
#define WARPS 12
#define NPW 8                // nodes per warp
#define SM_W (K2*D)          // floats of stacked weights [Wl;Wr]
#define STAGE_FLOATS (NPW*K2)
#define SMEM_BYTES ((SM_W + WARPS*STAGE_FLOATS)*4)   // 131072+98304 = 229376

// ---------------- scratch (device globals: no allocation allowed) ----------
__device__ int   g_deg[Nn];
__device__ int   g_off[Nn];
__device__ int   g_cur[Nn];
__device__ int   g_elist[Ee];
__device__ int   g_bsum[512];
__device__ __align__(16) float g_h[(size_t)Nn * D];
__device__ __align__(16) float g_mean[(size_t)Nn * D];
__device__ __align__(16) float g_bnsum[D];
__device__ __align__(16) float g_bnsq[D];
__device__ __align__(16) float g_bns[D];
__device__ __align__(16) float g_bnt[D];
__device__ float g_preds_fb[Nn];
__device__ __align__(16) float g_embed_fb[(size_t)Nn * D];

// ---------------- f32x2 packed math (Blackwell FFMA2, PTX-only path) -------
__device__ __forceinline__ unsigned long long fma2(unsigned long long a,
                                                   unsigned long long b,
                                                   unsigned long long c) {
    unsigned long long d;
    asm("fma.rn.f32x2 %0, %1, %2, %3;" : "=l"(d) : "l"(a), "l"(b), "l"(c));
    return d;
}
__device__ __forceinline__ unsigned long long pack2(float a) {
    unsigned long long d;
    asm("mov.b64 %0, {%1, %1};" : "=l"(d) : "f"(a));
    return d;
}
__device__ __forceinline__ float2 unpack2(unsigned long long v) {
    float2 r;
    asm("mov.b64 {%0, %1}, %2;" : "=f"(r.x), "=f"(r.y) : "l"(v));
    return r;
}

// ---------------- CSR build ------------------------------------------------
__global__ void k_zero() {
    int i = blockIdx.x * blockDim.x + threadIdx.x;
    if (i < Nn) g_deg[i] = 0;
    if (i < D) { g_bnsum[i] = 0.f; g_bnsq[i] = 0.f; }
}

__global__ void k_degree(const int* __restrict__ dst) {
    int e = blockIdx.x * blockDim.x + threadIdx.x;
    if (e < Ee) atomicAdd(&g_deg[dst[e]], 1);
}

__global__ void k_scan1() {
    __shared__ int s[256];
    int i = blockIdx.x * 256 + threadIdx.x;
    int v = (i < Nn) ? g_deg[i] : 0;
    s[threadIdx.x] = v; __syncthreads();
    for (int d = 128; d > 0; d >>= 1) {
        if (threadIdx.x < d) s[threadIdx.x] += s[threadIdx.x + d];
        __syncthreads();
    }
    if (threadIdx.x == 0) g_bsum[blockIdx.x] = s[0];
}

__global__ void k_scan2() {   // exclusive scan of 391 block sums, 1 block
    __shared__ int s[512];
    int t = threadIdx.x;
    int v = (t < NB_SCAN) ? g_bsum[t] : 0;
    s[t] = v; __syncthreads();
    for (int d = 1; d < 512; d <<= 1) {
        int x = (t >= d) ? s[t - d] : 0;
        __syncthreads();
        s[t] += x;
        __syncthreads();
    }
    if (t < NB_SCAN) g_bsum[t] = s[t] - v;   // exclusive
}

__global__ void k_scan3() {
    __shared__ int s[256];
    int t = threadIdx.x;
    int i = blockIdx.x * 256 + t;
    int v = (i < Nn) ? g_deg[i] : 0;
    s[t] = v; __syncthreads();
    for (int d = 1; d < 256; d <<= 1) {
        int x = (t >= d) ? s[t - d] : 0;
        __syncthreads();
        s[t] += x;
        __syncthreads();
    }
    if (i < Nn) {
        int off = g_bsum[blockIdx.x] + s[t] - v;
        g_off[i] = off;
        g_cur[i] = off;
    }
}

__global__ void k_fill(const int* __restrict__ src, const int* __restrict__ dst) {
    int e = blockIdx.x * blockDim.x + threadIdx.x;
    if (e < Ee) {
        int p = atomicAdd(&g_cur[dst[e]], 1);
        g_elist[p] = src[e];
    }
}

// ---------------- mean aggregation (warp per node, latency-hidden) ---------
__global__ __launch_bounds__(256)
void k_agg(const float* __restrict__ xin) {
    int w = (blockIdx.x * blockDim.x + threadIdx.x) >> 5;
    int lane = threadIdx.x & 31;
    if (w >= Nn) return;
    int off = g_off[w], dg = g_deg[w];
    const float4* xi4 = (const float4*)xin;
    float4 a0 = make_float4(0, 0, 0, 0), a1 = make_float4(0, 0, 0, 0);
    int e = 0;
    for (; e + 1 < dg; e += 2) {
        int s0 = __ldg(&g_elist[off + e]);
        int s1 = __ldg(&g_elist[off + e + 1]);
        float4 v0 = __ldg(&xi4[(size_t)s0 * 32 + lane]);
        float4 v1 = __ldg(&xi4[(size_t)s1 * 32 + lane]);
        a0.x += v0.x; a0.y += v0.y; a0.z += v0.z; a0.w += v0.w;
        a1.x += v1.x; a1.y += v1.y; a1.z += v1.z; a1.w += v1.w;
    }
    if (e < dg) {
        int s0 = __ldg(&g_elist[off + e]);
        float4 v0 = __ldg(&xi4[(size_t)s0 * 32 + lane]);
        a0.x += v0.x; a0.y += v0.y; a0.z += v0.z; a0.w += v0.w;
    }
    float inv = 1.f / (float)max(dg, 1);
    float4 m = make_float4((a0.x + a1.x) * inv, (a0.y + a1.y) * inv,
                           (a0.z + a1.z) * inv, (a0.w + a1.w) * inv);
    ((float4*)g_mean)[(size_t)w * 32 + lane] = m;
}

// ---------------- BN finalize ----------------------------------------------
__global__ void k_bnfin(const float* __restrict__ gamma,
                        const float* __restrict__ beta) {
    int j = threadIdx.x;
    if (j < D) {
        float mu  = g_bnsum[j] / (float)Nn;
        float var = g_bnsq[j] / (float)Nn - mu * mu;
        float s   = gamma[j] * rsqrtf(var + 1e-5f);
        g_bns[j] = s;
        g_bnt[j] = beta[j] - mu * s;
    }
}

// ---------------- fused SAGE layer (stacked GEMM + L2norm) -----------------
// A-row per node = [mean(0..127) | x(128..255)], weights stacked [Wl;Wr].
// 12 warps x NPW=8: per k4-step 64 FFMA2 vs 24 crossbar wavefronts (75% of
// fma cycles) -- fma-bound with margin.
__global__ __launch_bounds__(THREADS, 1)
void k_layer(const float* __restrict__ xin,
             const float* __restrict__ Wl, const float* __restrict__ bl,
             const float* __restrict__ Wr,
             float* __restrict__ hout, float* __restrict__ preds,
             const float* __restrict__ fcw, const float* __restrict__ fcb,
             int layer) {
    extern __shared__ float smem[];
    float* sW = smem;                  // [256][128] stacked
    float* sStage = smem + SM_W;

    int tid = threadIdx.x, warp = tid >> 5, lane = tid & 31;

    // Load stacked weight matrix into shared memory (float4 copies)
    {
        const float4* a = (const float4*)Wl;
        const float4* b = (const float4*)Wr;
        float4* dw = (float4*)sW;
        for (int i = tid; i < (D * D) / 4; i += THREADS) {
            dw[i] = a[i];
            dw[(D * D) / 4 + i] = b[i];
        }
    }
    float4 bias = ((const float4*)bl)[lane];
    float4 bns = make_float4(0, 0, 0, 0), bnt = make_float4(0, 0, 0, 0);
    if (layer == 2) {
        bns = ((const float4*)g_bns)[lane];
        bnt = ((const float4*)g_bnt)[lane];
    }
    __syncthreads();

    float lsum[4] = {0, 0, 0, 0}, lsq[4] = {0, 0, 0, 0};

    float* A = sStage + warp * STAGE_FLOATS;   // NPW rows of 256 floats

    const float4* xi4 = (const float4*)xin;
    const float4* mn4 = (const float4*)g_mean;
    const int ngroups = (Nn + NPW - 1) / NPW;

    for (int g = blockIdx.x * WARPS + warp; g < ngroups; g += gridDim.x * WARPS) {
        int base = g * NPW;
        __syncwarp();
        // ---- stage: coalesced mean + root row (per node, per-lane float4) --
        #pragma unroll
        for (int m = 0; m < NPW; m++) {
            int node = base + m;
            float4 mean = make_float4(0, 0, 0, 0);
            float4 xr   = make_float4(0, 0, 0, 0);
            if (node < Nn) {
                mean = __ldg(&mn4[(size_t)node * 32 + lane]);
                xr   = __ldg(&xi4[(size_t)node * 32 + lane]);
                if (layer == 2) {
                    // fold BN affine; mean over 0 neighbors stays 0
                    if (__ldg(&g_deg[node]) > 0) {
                        mean.x = mean.x * bns.x + bnt.x;
                        mean.y = mean.y * bns.y + bnt.y;
                        mean.z = mean.z * bns.z + bnt.z;
                        mean.w = mean.w * bns.w + bnt.w;
                    } else {
                        mean = make_float4(0, 0, 0, 0);
                    }
                    xr.x = xr.x * bns.x + bnt.x;
                    xr.y = xr.y * bns.y + bnt.y;
                    xr.z = xr.z * bns.z + bnt.z;
                    xr.w = xr.w * bns.w + bnt.w;
                }
            }
            ((float4*)(A + m * K2))[lane] = mean;          // cols 0..127
            ((float4*)(A + m * K2 + D))[lane] = xr;        // cols 128..255
        }
        __syncwarp();

        // ---- stacked GEMM: out = A[256] @ sW[256][128], f32x2 accumulators -
        unsigned long long accA[NPW], accB[NPW];
        #pragma unroll
        for (int m = 0; m < NPW; m++) { accA[m] = 0ull; accB[m] = 0ull; }

        const ulonglong2* wv = (const ulonglong2*)sW;   // 32 ulonglong2 per row
        #pragma unroll 2
        for (int k4 = 0; k4 < K2; k4 += 4) {
            ulonglong2 w0 = wv[(k4 + 0) * 32 + lane];   // W[k][4lane..4lane+3]
            ulonglong2 w1 = wv[(k4 + 1) * 32 + lane];
            ulonglong2 w2 = wv[(k4 + 2) * 32 + lane];
            ulonglong2 w3 = wv[(k4 + 3) * 32 + lane];
            #pragma unroll
            for (int m = 0; m < NPW; m++) {
                float4 a = *(const float4*)(A + m * K2 + k4);  // broadcast
                unsigned long long p0 = pack2(a.x);
                unsigned long long p1 = pack2(a.y);
                unsigned long long p2 = pack2(a.z);
                unsigned long long p3 = pack2(a.w);
                accA[m] = fma2(p0, w0.x, accA[m]); accB[m] = fma2(p0, w0.y, accB[m]);
                accA[m] = fma2(p1, w1.x, accA[m]); accB[m] = fma2(p1, w1.y, accB[m]);
                accA[m] = fma2(p2, w2.x, accA[m]); accB[m] = fma2(p2, w2.y, accB[m]);
                accA[m] = fma2(p3, w3.x, accA[m]); accB[m] = fma2(p3, w3.y, accB[m]);
            }
        }

        // ---- epilogue per node: bias, L2-normalize, layer-specific ---------
        #pragma unroll
        for (int m = 0; m < NPW; m++) {
            int node = base + m;
            if (node >= Nn) continue;   // uniform across warp
            float2 p0 = unpack2(accA[m]);
            float2 p1 = unpack2(accB[m]);
            float o0 = p0.x + bias.x;
            float o1 = p0.y + bias.y;
            float o2 = p1.x + bias.z;
            float o3 = p1.y + bias.w;
            float ss = o0 * o0 + o1 * o1 + o2 * o2 + o3 * o3;
            #pragma unroll
            for (int t = 16; t > 0; t >>= 1) ss += __shfl_xor_sync(0xffffffffu, ss, t);
            float inv = 1.f / fmaxf(sqrtf(ss), 1e-12f);
            o0 *= inv; o1 *= inv; o2 *= inv; o3 *= inv;
            if (layer == 1) {
                o0 = fmaxf(o0, 0.f); o1 = fmaxf(o1, 0.f);
                o2 = fmaxf(o2, 0.f); o3 = fmaxf(o3, 0.f);
                lsum[0] += o0; lsq[0] += o0 * o0;
                lsum[1] += o1; lsq[1] += o1 * o1;
                lsum[2] += o2; lsq[2] += o2 * o2;
                lsum[3] += o3; lsq[3] += o3 * o3;
                ((float4*)hout)[(size_t)node * 32 + lane] = make_float4(o0, o1, o2, o3);
            } else {
                ((float4*)hout)[(size_t)node * 32 + lane] = make_float4(o0, o1, o2, o3);
                float p = 0.f;
                if (lane < 16) {
                    int j = 4 * lane;
                    p = o0 * fcw[j] + o1 * fcw[j + 1] + o2 * fcw[j + 2] + o3 * fcw[j + 3];
                }
                #pragma unroll
                for (int t = 8; t > 0; t >>= 1) p += __shfl_down_sync(0xffffffffu, p, t);
                if (lane == 0) preds[node] = p + fcb[0];
            }
        }
    }

    // ---- BN stats: block-reduce then 128 global atomics per block ----------
    if (layer == 1) {
        __syncthreads();
        float* bs  = smem;
        float* bss = smem + 128;
        if (tid < 256) { bs[tid] = 0.f; }
        __syncthreads();
        #pragma unroll
        for (int i = 0; i < 4; i++) {
            atomicAdd(&bs[4 * lane + i], lsum[i]);
            atomicAdd(&bss[4 * lane + i], lsq[i]);
        }
        __syncthreads();
        if (tid < 128) {
            atomicAdd(&g_bnsum[tid], bs[tid]);
            atomicAdd(&g_bnsq[tid], bss[tid]);
        }
    }
}

// ---------------- launch ----------------------------------------------------
extern "C" void kernel_launch(void* const* d_in, const int* in_sizes, int n_in,
                              void* d_out, int out_size) {
    const float* x     = (const float*)d_in[0];
    const int*   ei    = (const int*)d_in[1];
    const int*   src   = ei;
    const int*   dst   = ei + Ee;
    const float* W1l   = (const float*)d_in[2];
    const float* b1l   = (const float*)d_in[3];
    const float* W1r   = (const float*)d_in[4];
    const float* gamma = (const float*)d_in[5];
    const float* beta  = (const float*)d_in[6];
    const float* W2l   = (const float*)d_in[7];
    const float* b2l   = (const float*)d_in[8];
    const float* W2r   = (const float*)d_in[9];
    const float* fcw   = (const float*)d_in[10];
    const float* fcb   = (const float*)d_in[11];

    float* ph = nullptr;
    cudaGetSymbolAddress((void**)&ph, g_h);

    float* out = (float*)d_out;
    float* preds;
    float* embed;
    if (out_size == Nn + Nn * D) {            // (preds, embed) concatenated
        preds = out;
        embed = out + Nn;
    } else if (out_size == Nn * D) {          // embed only
        embed = out;
        cudaGetSymbolAddress((void**)&preds, g_preds_fb);
    } else {                                   // preds only (or unknown)
        preds = out;
        cudaGetSymbolAddress((void**)&embed, g_embed_fb);
    }

    int sms = 148;
    cudaDeviceGetAttribute(&sms, cudaDevAttrMultiProcessorCount, 0);

    cudaFuncSetAttribute(k_layer, cudaFuncAttributeMaxDynamicSharedMemorySize,
                         SMEM_BYTES);

    k_zero<<<(Nn + 255) / 256, 256>>>();
    k_degree<<<(Ee + 255) / 256, 256>>>(dst);
    k_scan1<<<NB_SCAN, 256>>>();
    k_scan2<<<1, 512>>>();
    k_scan3<<<NB_SCAN, 256>>>();
    k_fill<<<(Ee + 255) / 256, 256>>>(src, dst);

    k_agg<<<(Nn * 32 + 255) / 256, 256>>>(x);
    k_layer<<<sms, THREADS, SMEM_BYTES>>>(x, W1l, b1l, W1r, ph,
                                          nullptr, nullptr, nullptr, 1);
    k_bnfin<<<1, 128>>>(gamma, beta);
    k_agg<<<(Nn * 32 + 255) / 256, 256>>>(ph);
    k_layer<<<sms, THREADS, SMEM_BYTES>>>(ph, W2l, b2l, W2r, embed,
                                          preds, fcw, fcb, 2);
}